// round 12
// baseline (speedup 1.0000x reference)
#include <cuda_runtime.h>
#include <cuda_fp16.h>
#include <math.h>

#define BATCH 16
#define IMH 768
#define IMW 768
#define TILE_W 32
#define TILE_H 64
#define R3 9
#define LOAD_W 50            // TILE_W + 18
#define LOAD_H 82            // TILE_H + 18
#define XSTR 51              // half2 raw tile stride (odd -> conflict-free)
#define USTR 51              // half u tile stride
#define HSTR 33              // blurred plane stride
#define H1ROWS 70            // TILE_H + 6
#define XF_ROWS 66           // fp32 gradient patch rows (TILE_H + 2)
#define XF_COLS 34
#define XFSTR 35
#define NBINS 512
#define NWORDS (NBINS/2)
#define NTHREADS 512
#define NWARPS (NTHREADS/32)
#define NACC 15
#define GRID_BLOCKS ((IMW/TILE_W)*(IMH/TILE_H)*BATCH)   // 24*12*16 = 4608

// byte offsets in dynamic smem
#define OFF_XY   0                                 // half2[82*51] = 16728 B
#define OFF_H3   (OFF_XY + LOAD_H*XSTR*4)          // half2[82*33] = 10824 B
#define OFF_H3U  (OFF_H3 + LOAD_H*HSTR*4)          // half [82*33] =  5412 B
#define OFF_U    (OFF_H3U + LOAD_H*HSTR*2)         // half [82*51] =  8364 B
#define OFF_H1   (OFF_U + LOAD_H*USTR*2)           // half2[70*33] =  9240 B
#define OFF_HIST (OFF_H1 + H1ROWS*HSTR*4)          // u32 [512]    =  2048 B
#define OFF_XF   (OFF_HIST + 2*NWORDS*4)           // f32 [66*35]  =  9240 B
#define OFF_YF   (OFF_XF + XF_ROWS*XFSTR*4)        // f32 [66*35]  =  9240 B
#define SMEM_BYTES (OFF_YF + XF_ROWS*XFSTR*4)      // 71096 B

#define NH3 (LOAD_H*8)               // 656 G3-h work items
#define NH1 (H1ROWS*8)               // 560 G1-h work items

__device__ constexpr float G3W[19] = {
    0.00147944f, 0.00380430f, 0.00875341f, 0.01802349f, 0.03320783f,
    0.05475024f, 0.08077522f, 0.10663890f, 0.12597909f, 0.13317587f,
    0.12597909f, 0.10663890f, 0.08077522f, 0.05475024f, 0.03320783f,
    0.01802349f, 0.00875341f, 0.00380430f, 0.00147944f };
__device__ constexpr float G1W[7] = {
    0.00443305f, 0.05400558f, 0.24203623f, 0.39905027f,
    0.24203623f, 0.05400558f, 0.00443305f };

__device__ double       g_acc[NACC];
__device__ unsigned int g_histp[2*NWORDS];
__device__ unsigned int g_ticket;

__global__ __launch_bounds__(NTHREADS, 2)
void main_kernel(const float* __restrict__ yp_g,
                 const float* __restrict__ np_g,
                 const float* __restrict__ xi_g,
                 const float* __restrict__ xm_g,
                 const float* __restrict__ wt_g,
                 const float* __restrict__ ns_g,
                 float* __restrict__ out)
{
    extern __shared__ char smem_raw[];
    __half2* s_xy  = (__half2*)(smem_raw + OFF_XY);
    __half2* s_h3  = (__half2*)(smem_raw + OFF_H3);
    __half*  s_h3u = (__half*)(smem_raw + OFF_H3U);
    __half*  s_u   = (__half*)(smem_raw + OFF_U);
    __half2* s_h1  = (__half2*)(smem_raw + OFF_H1);
    unsigned int* s_hist = (unsigned int*)(smem_raw + OFF_HIST);
    float* s_xf = (float*)(smem_raw + OFF_XF);
    float* s_yf = (float*)(smem_raw + OFF_YF);

    __shared__ float s_part[NACC][NWARPS];
    __shared__ unsigned int s_wtot[NWARPS];
    __shared__ double s_q[4];
    __shared__ bool s_last;

    const int tid = threadIdx.x;
    for (int i = tid; i < 2*NWORDS; i += NTHREADS) s_hist[i] = 0u;

    __half2 w3[19], w1[7];
    __half  w3s[19];
    #pragma unroll
    for (int t = 0; t < 19; t++) { w3[t] = __float2half2_rn(G3W[t]); w3s[t] = __float2half_rn(G3W[t]); }
    #pragma unroll
    for (int t = 0; t < 7; t++)  { w1[t] = __float2half2_rn(G1W[t]); }

    const int oy = blockIdx.y * TILE_H;
    const int ox = blockIdx.x * TILE_W;
    const int img = blockIdx.z * (IMH * IMW);

    // ---- load raw tiles; fp32 gradient patches for raw (r,c) in [8,73]x[8,41] ----
    for (int i = tid; i < LOAD_H*LOAD_W; i += NTHREADS) {
        int r = i / LOAD_W, c = i - r * LOAD_W;
        int gy = oy + r - R3, gx = ox + c - R3;
        bool in = ((unsigned)gy < IMH) & ((unsigned)gx < IMW);
        float vx = 0.f, vy = 0.f, vm = 0.f;
        if (in) {
            int g = img + gy * IMW + gx;
            vx = xi_g[g]; vy = yp_g[g]; vm = xm_g[g];
        }
        s_xy[r*XSTR + c] = __floats2half2_rn(vx, vy);
        s_u [r*USTR + c] = __float2half_rn(fmaf(-0.7f, vm, fmaf(-0.3f, vx, vy)));
        if (((unsigned)(r - 8) < XF_ROWS) & ((unsigned)(c - 8) < XF_COLS)) {
            int o = (r - 8)*XFSTR + (c - 8);
            s_xf[o] = vx;
            s_yf[o] = vy;
        }
    }
    __syncthreads();

    // ---- merged horizontal passes (G3 on xy+u, G1 on xy), one barrier ----
    for (int i = tid; i < NH3 + NH1; i += NTHREADS) {
        if (i < NH3) {
            int r = i >> 3, c4 = (i & 7) << 2;
            int bx = r*XSTR + c4, bu = r*USTR + c4;
            __half2 a0 = __float2half2_rn(0.f), a1 = a0, a2 = a0, a3 = a0;
            __half  m0 = __float2half_rn(0.f), m1 = m0, m2 = m0, m3 = m0;
            #pragma unroll
            for (int t = 0; t < 22; t++) {
                __half2 v = s_xy[bx + t];
                __half vu = s_u[bu + t];
                if (t <= 18)           { a0 = __hfma2(v, w3[t  ], a0); m0 = __hfma(vu, w3s[t  ], m0); }
                if (t >= 1 && t <= 19) { a1 = __hfma2(v, w3[t-1], a1); m1 = __hfma(vu, w3s[t-1], m1); }
                if (t >= 2 && t <= 20) { a2 = __hfma2(v, w3[t-2], a2); m2 = __hfma(vu, w3s[t-2], m2); }
                if (t >= 3)            { a3 = __hfma2(v, w3[t-3], a3); m3 = __hfma(vu, w3s[t-3], m3); }
            }
            int o = r*HSTR + c4;
            s_h3[o]=a0; s_h3[o+1]=a1; s_h3[o+2]=a2; s_h3[o+3]=a3;
            s_h3u[o]=m0; s_h3u[o+1]=m1; s_h3u[o+2]=m2; s_h3u[o+3]=m3;
        } else {
            int j = i - NH3;
            int r = j >> 3, c4 = (j & 7) << 2;
            int bx = (r + 6)*XSTR + c4 + 6;
            __half2 a0 = __float2half2_rn(0.f), a1 = a0, a2 = a0, a3 = a0;
            #pragma unroll
            for (int t = 0; t < 10; t++) {
                __half2 v = s_xy[bx + t];
                if (t <= 6)           { a0 = __hfma2(v, w1[t  ], a0); }
                if (t >= 1 && t <= 7) { a1 = __hfma2(v, w1[t-1], a1); }
                if (t >= 2 && t <= 8) { a2 = __hfma2(v, w1[t-2], a2); }
                if (t >= 3)           { a3 = __hfma2(v, w1[t-3], a3); }
            }
            int o = r*HSTR + c4;
            s_h1[o]=a0; s_h1[o+1]=a1; s_h1[o+2]=a2; s_h1[o+3]=a3;
        }
    }
    __syncthreads();

    // ---- per-pixel phase: thread owns column c, rows r0..r0+3 (16 groups) ----
    const int c  = tid & 31;
    const int r0 = (tid >> 5) << 2;

    __half2 LIP[4]; __half LU[4];
    #pragma unroll
    for (int j = 0; j < 4; j++) { LIP[j] = __float2half2_rn(0.f); LU[j] = __float2half_rn(0.f); }
    #pragma unroll
    for (int t = 0; t < 22; t++) {
        int idx = (r0 + t)*HSTR + c;
        __half2 v = s_h3[idx];
        __half vu = s_h3u[idx];
        if (t <= 18)           { LIP[0]=__hfma2(v,w3[t  ],LIP[0]); LU[0]=__hfma(vu,w3s[t  ],LU[0]); }
        if (t >= 1 && t <= 19) { LIP[1]=__hfma2(v,w3[t-1],LIP[1]); LU[1]=__hfma(vu,w3s[t-1],LU[1]); }
        if (t >= 2 && t <= 20) { LIP[2]=__hfma2(v,w3[t-2],LIP[2]); LU[2]=__hfma(vu,w3s[t-2],LU[2]); }
        if (t >= 3)            { LIP[3]=__hfma2(v,w3[t-3],LIP[3]); LU[3]=__hfma(vu,w3s[t-3],LU[3]); }
    }
    __half2 G1P[4];
    #pragma unroll
    for (int j = 0; j < 4; j++) G1P[j] = __float2half2_rn(0.f);
    #pragma unroll
    for (int t = 0; t < 10; t++) {
        __half2 v = s_h1[(r0 + t)*HSTR + c];
        if (t <= 6)           { G1P[0]=__hfma2(v,w1[t  ],G1P[0]); }
        if (t >= 1 && t <= 7) { G1P[1]=__hfma2(v,w1[t-1],G1P[1]); }
        if (t >= 2 && t <= 8) { G1P[2]=__hfma2(v,w1[t-2],G1P[2]); }
        if (t >= 3)           { G1P[3]=__hfma2(v,w1[t-3],G1P[3]); }
    }

    float p_rc=0,p_nb=0,p_sxi=0,p_syp=0,p_ex=0,p_ey=0,p_ntex=0,p_stex=0;
    float p_nf=0,p_nfb=0,p_lf=0,p_mid=0,p_hf=0,p_syn=0,p_ic=0;

    // fp32 rolling 3x3 windows from the gradient patches
    int fb = r0*XFSTR + c;
    float x00=s_xf[fb],       x01=s_xf[fb+1],       x02=s_xf[fb+2];
    float y00=s_yf[fb],       y01=s_yf[fb+1],       y02=s_yf[fb+2];
    float x10=s_xf[fb+XFSTR], x11=s_xf[fb+XFSTR+1], x12=s_xf[fb+XFSTR+2];
    float y10=s_yf[fb+XFSTR], y11=s_yf[fb+XFSTR+1], y12=s_yf[fb+XFSTR+2];

    #pragma unroll
    for (int j = 0; j < 4; j++) {
        int fbn = fb + (j+2)*XFSTR;
        float x20=s_xf[fbn], x21=s_xf[fbn+1], x22=s_xf[fbn+2];
        float y20=s_yf[fbn], y21=s_yf[fbn+1], y22=s_yf[fbn+2];

        float gxi = (x02 - x00) + 2.f*(x12 - x10) + (x22 - x20);
        float gyi = (x20 - x00) + 2.f*(x21 - x01) + (x22 - x02);
        float lap_i = x01 + x10 + x12 + x21 - 4.f*x11;
        float gxp = (y02 - y00) + 2.f*(y12 - y10) + (y22 - y20);
        float gyp = (y20 - y00) + 2.f*(y21 - y01) + (y22 - y02);
        float lap_p = y01 + y10 + y12 + y21 - 4.f*y11;

        float xi = x11, yp = y11;

        int g = img + (oy + r0 + j)*IMW + (ox + c);
        float wv   = wt_g[g];
        float nprd = np_g[g];
        float nsyn = ns_g[g];

        p_rc += fabsf(yp*wv - xi*wv);

        bool body = (xi > 0.15f) & (xi < 0.85f);
        if (body) {
            p_nb += 1.f; p_sxi += xi; p_syp += yp;
            int b1 = min(max((int)(yp * (float)NBINS), 0), NBINS-1);
            atomicAdd(&s_hist[b1 >> 1], 1u << ((b1 & 1) * 16));
            int b2 = min(max((int)(xi * (float)NBINS), 0), NBINS-1);
            atomicAdd(&s_hist[NWORDS + (b2 >> 1)], 1u << ((b2 & 1) * 16));
        }

        p_ex += fabsf(gxp - gxi);
        p_ey += fabsf(gyp - gyi);

        float gmi = sqrtf(fmaf(gxi,gxi, gyi*gyi) + 1e-8f);
        float gmp = sqrtf(fmaf(gxp,gxp, gyp*gyp) + 1e-8f);

        bool tex = (gmi > 0.03f) & (gmi < 0.5f);
        if (tex) { p_ntex += 1.f; p_stex += fabsf(gmp - gmi); }

        bool flat = (gmi < 0.03f);
        if (flat) {
            p_nf += 1.f;
            p_hf += fabsf(fabsf(lap_p) - 0.3f*fabsf(lap_i));
            p_ic += fmaxf(gmp - 2.0f*gmi, 0.f);
            if (body) {
                p_nfb += 1.f;
                p_lf  += fabsf(__half2float(LU[j]));
                float low_i = __low2float(LIP[j]), low_p = __high2float(LIP[j]);
                float g1i   = __low2float(G1P[j]), g1p   = __high2float(G1P[j]);
                p_mid += fabsf(fabsf(g1p - low_p) - 0.3f*fabsf(g1i - low_i));
                p_syn += fabsf(nprd - nsyn);
            }
        }

        x00=x10; x01=x11; x02=x12; x10=x20; x11=x21; x12=x22;
        y00=y10; y01=y11; y02=y12; y10=y20; y11=y21; y12=y22;
    }

    // ---- block reduction of 15 partials (16 warps) ----
    float vals[NACC] = {p_rc, p_nb, p_sxi, p_syp, p_ex, p_ey, p_ntex, p_stex,
                        p_nf, p_nfb, p_lf, p_mid, p_hf, p_syn, p_ic};
    int lane = tid & 31, warp = tid >> 5;
    #pragma unroll
    for (int q = 0; q < NACC; q++) {
        float v = vals[q];
        #pragma unroll
        for (int o = 16; o > 0; o >>= 1) v += __shfl_down_sync(0xffffffffu, v, o);
        if (lane == 0) s_part[q][warp] = v;
    }
    __syncthreads();
    if (tid < NACC) {
        float s = 0.f;
        #pragma unroll
        for (int w = 0; w < NWARPS; w++) s += s_part[tid][w];
        atomicAdd(&g_acc[tid], (double)s);
    }
    for (int i = tid; i < 2*NWORDS; i += NTHREADS) {
        unsigned int h = s_hist[i];
        if (h) atomicAdd(&g_histp[i], h);
    }

    // ---- last-block finalize ----
    __syncthreads();
    if (tid == 0) {
        __threadfence();
        unsigned t = atomicAdd(&g_ticket, 1u);
        s_last = (t == GRID_BLOCKS - 1);
    }
    __syncthreads();
    if (!s_last) return;
    __threadfence();

    unsigned int* s_cum = s_hist;
    const double nb = g_acc[1];

    for (int h = 0; h < 2; h++) {
        unsigned int w0 = (tid < NWORDS) ? g_histp[h*NWORDS + tid] : 0u;
        unsigned int lo = w0 & 0xffffu, hi = w0 >> 16;
        unsigned int run = lo + hi;
        unsigned int v = run;
        #pragma unroll
        for (int o = 1; o < 32; o <<= 1) {
            unsigned int u = __shfl_up_sync(0xffffffffu, v, o);
            if (lane >= o) v += u;
        }
        __syncthreads();
        if (lane == 31) s_wtot[warp] = v;
        __syncthreads();
        if (tid < NWORDS) {
            unsigned int woff = 0;
            for (int w = 0; w < warp; w++) woff += s_wtot[w];
            unsigned int off = woff + v - run;
            s_cum[2*tid]   = off + lo;
            s_cum[2*tid+1] = off + run;
        }
        __syncthreads();
        if (tid < 2) {
            double q = (tid == 0) ? 0.25 : 0.75;
            double pos = q * (nb - 1.0);
            int lo_i = 0, hi_i = NBINS - 1;
            while (lo_i < hi_i) {
                int m = (lo_i + hi_i) >> 1;
                if ((double)s_cum[m] > pos) hi_i = m; else lo_i = m + 1;
            }
            int b = lo_i;
            unsigned int cb = s_cum[b];
            unsigned int pv = b ? s_cum[b-1] : 0u;
            double cnt = (double)(cb - pv);
            double val = 0.0;
            if (cnt > 0.0) {
                double frac = (pos - (double)pv + 0.5) / cnt;
                frac = fmin(fmax(frac, 0.0), 1.0);
                val = ((double)b + frac) / (double)NBINS;
            }
            s_q[h*2 + tid] = val;
        }
        __syncthreads();
    }

    if (tid == 0) {
        const double n_all = (double)BATCH * IMH * IMW;
        double rc = g_acc[0] / n_all;
        double denb = fmax(nb, 1.0);
        double mean_in = g_acc[2] / denb;
        double mean_pr = g_acc[3] / denb;
        double dm  = mean_pr - mean_in;
        double d25 = s_q[0] - s_q[2];
        double d75 = s_q[1] - s_q[3];
        double hu  = dm*dm + 0.5*(d25*d25 + d75*d75);
        double loss_hu = (nb > 4096.0) ? hu : 0.0;
        double edge = g_acc[4]/n_all + g_acc[5]/n_all;
        double ntex = g_acc[6];
        double tex = (ntex > 100.0) ? g_acc[7]/fmax(ntex, 1.0) : 0.0;
        double nf = g_acc[8], nfb = g_acc[9];
        double lf  = (nfb > 100.0) ? g_acc[10]/fmax(nfb, 1.0) : 0.0;
        double mid = (nfb > 100.0) ? g_acc[11]/fmax(nfb, 1.0) : 0.0;
        double hf  = (nf  > 100.0) ? g_acc[12]/fmax(nf, 1.0)  : 0.0;
        double syn = (nfb > 100.0) ? g_acc[13]/fmax(nfb, 1.0) : 0.0;
        double ic  = (nf  > 100.0) ? g_acc[14]/fmax(nf, 1.0)  : 0.0;

        double total = 2.0*rc + 1.5*loss_hu + 1.0*edge + 0.8*tex
                     + 1.5*hf + 0.8*mid + 0.6*lf + 1.0*syn + 0.8*ic;
        out[0] = (float)total;
    }
    __syncthreads();

    for (int i = tid; i < 2*NWORDS; i += NTHREADS) g_histp[i] = 0u;
    if (tid < NACC) g_acc[tid] = 0.0;
    if (tid == 0) g_ticket = 0u;
}

extern "C" void kernel_launch(void* const* d_in, const int* in_sizes, int n_in,
                              void* d_out, int out_size) {
    const float* yp = (const float*)d_in[0];   // y_pred
    const float* np = (const float*)d_in[1];   // noise_pred
    const float* xi = (const float*)d_in[2];   // x_i
    // d_in[3] = x_ip1 (unused by reference)
    const float* xm = (const float*)d_in[4];   // x_mid
    const float* wt = (const float*)d_in[5];   // W
    const float* ns = (const float*)d_in[6];   // noise_synthetic
    float* out = (float*)d_out;

    cudaFuncSetAttribute(main_kernel,
                         cudaFuncAttributeMaxDynamicSharedMemorySize, SMEM_BYTES);

    dim3 grid(IMW / TILE_W, IMH / TILE_H, BATCH);
    main_kernel<<<grid, NTHREADS, SMEM_BYTES>>>(yp, np, xi, xm, wt, ns, out);
}

// round 14
// speedup vs baseline: 1.0424x; 1.0424x over previous
#include <cuda_runtime.h>
#include <cuda_fp16.h>
#include <math.h>

#define BATCH 16
#define IMH 768
#define IMW 768
#define TILE 32
#define R3 9
#define LOAD 50
#define XW 52                // raw tile stride: half2 words (xy) / halves (u)
#define CS_XY 52             // xyT column stride (half2 words), ==4 mod 8 -> conflict-free LDS.128
#define CS_U  52             // uT column stride (halves); 26 words, ==2 mod 4 -> conflict-free LDS.64
#define CS_H1 44             // h1T column stride (half2 words), ==4 mod 8
#define H1ROWS 38
#define XF_ROWS 34
#define XFSTR 35
#define NBINS 512
#define NWORDS (NBINS/2)
#define NTHREADS 256
#define NACC 15
#define GRID_BLOCKS ((IMW/TILE)*(IMH/TILE)*BATCH)   // 9216

// smem byte offsets (16B-aligned where wide loads occur)
#define OFF_XY   0                              // half2[50*52] = 10400
#define OFF_U    (OFF_XY + LOAD*XW*4)           // half [50*52] =  5200
#define OFF_XYT  (OFF_U + LOAD*XW*2)            // half2[32*52] =  6656
#define OFF_UT   (OFF_XYT + 32*CS_XY*4)         // half [32*52] =  3328
#define OFF_H1T  (OFF_UT + 32*CS_U*2)           // half2[32*44] =  5632
#define OFF_HIST (OFF_H1T + 32*CS_H1*4)         // u32[512]     =  2048
#define OFF_XF   (OFF_HIST + 2*NWORDS*4)        // f32[34*35]   =  4760
#define OFF_YF   (OFF_XF + XF_ROWS*XFSTR*4)     // f32[34*35]   =  4760
#define SMEM_BYTES (OFF_YF + XF_ROWS*XFSTR*4)   // 42784

#define NH3 400              // G3-h items: 50 rows x 8 col-groups
#define NH1 304              // G1-h items: 38 rows x 8 col-groups

__device__ constexpr float G3W[19] = {
    0.00147944f, 0.00380430f, 0.00875341f, 0.01802349f, 0.03320783f,
    0.05475024f, 0.08077522f, 0.10663890f, 0.12597909f, 0.13317587f,
    0.12597909f, 0.10663890f, 0.08077522f, 0.05475024f, 0.03320783f,
    0.01802349f, 0.00875341f, 0.00380430f, 0.00147944f };
__device__ constexpr float G1W[7] = {
    0.00443305f, 0.05400558f, 0.24203623f, 0.39905027f,
    0.24203623f, 0.05400558f, 0.00443305f };

__device__ double       g_acc[NACC];
__device__ unsigned int g_histp[2*NWORDS];
__device__ unsigned int g_ticket;

__device__ __forceinline__ __half2 u2h2(unsigned u) {
    return *reinterpret_cast<__half2*>(&u);
}

__global__ __launch_bounds__(NTHREADS, 4)
void main_kernel(const float* __restrict__ yp_g,
                 const float* __restrict__ np_g,
                 const float* __restrict__ xi_g,
                 const float* __restrict__ xm_g,
                 const float* __restrict__ wt_g,
                 const float* __restrict__ ns_g,
                 float* __restrict__ out)
{
    extern __shared__ char smem_raw[];
    __half2* s_xy  = (__half2*)(smem_raw + OFF_XY);
    __half*  s_u   = (__half*)(smem_raw + OFF_U);
    __half2* s_xyT = (__half2*)(smem_raw + OFF_XYT);
    __half2* s_h1T = (__half2*)(smem_raw + OFF_H1T);
    unsigned int* s_hist = (unsigned int*)(smem_raw + OFF_HIST);
    float* s_xf = (float*)(smem_raw + OFF_XF);
    float* s_yf = (float*)(smem_raw + OFF_YF);

    __shared__ float s_part[NACC][8];
    __shared__ unsigned int s_wtot[8];
    __shared__ double s_q[4];
    __shared__ bool s_last;

    const int tid = threadIdx.x;
    for (int i = tid; i < 2*NWORDS; i += NTHREADS) s_hist[i] = 0u;

    __half2 w3[19], w1[7];
    __half  w3s[19];
    #pragma unroll
    for (int t = 0; t < 19; t++) { w3[t] = __float2half2_rn(G3W[t]); w3s[t] = __float2half_rn(G3W[t]); }
    #pragma unroll
    for (int t = 0; t < 7; t++)  { w1[t] = __float2half2_rn(G1W[t]); }

    const int oy = blockIdx.y * TILE;
    const int ox = blockIdx.x * TILE;
    const int img = blockIdx.z * (IMH * IMW);

    // ---- fill raw tiles (+ fp32 gradient patches for raw (r,c) in [8,41]^2) ----
    for (int i = tid; i < LOAD*LOAD; i += NTHREADS) {
        int r = i / LOAD, c = i - r * LOAD;
        int gy = oy + r - R3, gx = ox + c - R3;
        bool in = ((unsigned)gy < IMH) & ((unsigned)gx < IMW);
        float vx = 0.f, vy = 0.f, vm = 0.f;
        if (in) {
            int g = img + gy * IMW + gx;
            vx = xi_g[g]; vy = yp_g[g]; vm = xm_g[g];
        }
        s_xy[r*XW + c] = __floats2half2_rn(vx, vy);
        s_u [r*XW + c] = __float2half_rn(fmaf(-0.7f, vm, fmaf(-0.3f, vx, vy)));
        if (((unsigned)(r - 8) < XF_ROWS) & ((unsigned)(c - 8) < XF_ROWS)) {
            int o = (r - 8)*XFSTR + (c - 8);
            s_xf[o] = vx;
            s_yf[o] = vy;
        }
    }
    __syncthreads();

    // ---- merged horizontal passes, wide loads, transposed stores ----
    const uint4* xy4 = (const uint4*)(smem_raw + OFF_XY);
    const uint2* uu2 = (const uint2*)(smem_raw + OFF_U);
    for (int i = tid; i < NH3 + NH1; i += NTHREADS) {
        if (i < NH3) {
            int r = i % 50;
            int c4 = (i / 50) << 2;
            int bx = (r*XW + c4) >> 2;   // uint4 index (16B aligned: r*52+c4 ≡ 0 mod 4)
            __half2 xv[24];
            #pragma unroll
            for (int ch = 0; ch < 6; ch++) {
                uint4 q = xy4[bx + ch];
                xv[ch*4+0] = u2h2(q.x); xv[ch*4+1] = u2h2(q.y);
                xv[ch*4+2] = u2h2(q.z); xv[ch*4+3] = u2h2(q.w);
            }
            __half uv[24];
            #pragma unroll
            for (int ch = 0; ch < 6; ch++) {
                uint2 p = uu2[bx + ch];   // same index scale: halves/4
                __half2 h0 = u2h2(p.x), h1v = u2h2(p.y);
                uv[ch*4+0] = __low2half(h0);  uv[ch*4+1] = __high2half(h0);
                uv[ch*4+2] = __low2half(h1v); uv[ch*4+3] = __high2half(h1v);
            }
            __half2 a0 = __float2half2_rn(0.f), a1 = a0, a2 = a0, a3 = a0;
            __half  m0 = __float2half_rn(0.f), m1 = m0, m2 = m0, m3 = m0;
            #pragma unroll
            for (int t = 0; t < 22; t++) {
                __half2 v = xv[t]; __half vu = uv[t];
                if (t <= 18)           { a0 = __hfma2(v, w3[t  ], a0); m0 = __hfma(vu, w3s[t  ], m0); }
                if (t >= 1 && t <= 19) { a1 = __hfma2(v, w3[t-1], a1); m1 = __hfma(vu, w3s[t-1], m1); }
                if (t >= 2 && t <= 20) { a2 = __hfma2(v, w3[t-2], a2); m2 = __hfma(vu, w3s[t-2], m2); }
                if (t >= 3)            { a3 = __hfma2(v, w3[t-3], a3); m3 = __hfma(vu, w3s[t-3], m3); }
            }
            s_xyT[(c4+0)*CS_XY + r] = a0;
            s_xyT[(c4+1)*CS_XY + r] = a1;
            s_xyT[(c4+2)*CS_XY + r] = a2;
            s_xyT[(c4+3)*CS_XY + r] = a3;
            // pack u-blur halves across row pairs (i even <=> r even; partner = lane^1)
            unsigned amask = __activemask();
            unsigned ms[4] = { (unsigned)__half_as_ushort(m0), (unsigned)__half_as_ushort(m1),
                               (unsigned)__half_as_ushort(m2), (unsigned)__half_as_ushort(m3) };
            #pragma unroll
            for (int k = 0; k < 4; k++) {
                unsigned other = __shfl_xor_sync(amask, ms[k], 1);
                if ((i & 1) == 0) {
                    unsigned w = ms[k] | (other << 16);
                    ((unsigned*)(smem_raw + OFF_UT))[((c4+k)*CS_U + r) >> 1] = w;
                }
            }
        } else {
            int j = i - NH3;
            int r = j % 38;
            int c4 = (j / 38) << 2;
            int bx = ((r + 6)*XW + c4 + 4) >> 2;  // aligned; covers cols c4+4 .. c4+19
            __half2 xg[16];
            #pragma unroll
            for (int ch = 0; ch < 4; ch++) {
                uint4 q = xy4[bx + ch];
                xg[ch*4+0] = u2h2(q.x); xg[ch*4+1] = u2h2(q.y);
                xg[ch*4+2] = u2h2(q.z); xg[ch*4+3] = u2h2(q.w);
            }
            // tap t (0..9) is at element t+2 (col c4+6+t)
            __half2 a0 = __float2half2_rn(0.f), a1 = a0, a2 = a0, a3 = a0;
            #pragma unroll
            for (int t = 0; t < 10; t++) {
                __half2 v = xg[t + 2];
                if (t <= 6)           { a0 = __hfma2(v, w1[t  ], a0); }
                if (t >= 1 && t <= 7) { a1 = __hfma2(v, w1[t-1], a1); }
                if (t >= 2 && t <= 8) { a2 = __hfma2(v, w1[t-2], a2); }
                if (t >= 3)           { a3 = __hfma2(v, w1[t-3], a3); }
            }
            s_h1T[(c4+0)*CS_H1 + r] = a0;
            s_h1T[(c4+1)*CS_H1 + r] = a1;
            s_h1T[(c4+2)*CS_H1 + r] = a2;
            s_h1T[(c4+3)*CS_H1 + r] = a3;
        }
    }
    __syncthreads();

    // ---- per-pixel phase: thread owns column c, rows r0..r0+3 ----
    const int c  = tid & 31;
    const int r0 = (tid >> 5) << 2;

    __half2 LIP[4]; __half LU[4];
    #pragma unroll
    for (int j = 0; j < 4; j++) { LIP[j] = __float2half2_rn(0.f); LU[j] = __float2half_rn(0.f); }

    {   // vertical G3 on xy, wide column reads
        const uint4* xyT4 = (const uint4*)(smem_raw + OFF_XYT);
        int b = (c*CS_XY + r0) >> 2;
        #pragma unroll
        for (int ch = 0; ch < 6; ch++) {
            uint4 q = xyT4[b + ch];
            __half2 rv[4] = { u2h2(q.x), u2h2(q.y), u2h2(q.z), u2h2(q.w) };
            #pragma unroll
            for (int k = 0; k < 4; k++) {
                int t = ch*4 + k;
                if (t > 21) break;
                __half2 v = rv[k];
                if (t <= 18)           LIP[0] = __hfma2(v, w3[t  ], LIP[0]);
                if (t >= 1 && t <= 19) LIP[1] = __hfma2(v, w3[t-1], LIP[1]);
                if (t >= 2 && t <= 20) LIP[2] = __hfma2(v, w3[t-2], LIP[2]);
                if (t >= 3)            LIP[3] = __hfma2(v, w3[t-3], LIP[3]);
            }
        }
    }
    {   // vertical G3 on u
        const uint2* uT2 = (const uint2*)(smem_raw + OFF_UT);
        int b = (c*CS_U + r0) >> 2;
        #pragma unroll
        for (int ch = 0; ch < 6; ch++) {
            uint2 p = uT2[b + ch];
            __half2 h0 = u2h2(p.x), h1v = u2h2(p.y);
            __half rv[4] = { __low2half(h0), __high2half(h0),
                             __low2half(h1v), __high2half(h1v) };
            #pragma unroll
            for (int k = 0; k < 4; k++) {
                int t = ch*4 + k;
                if (t > 21) break;
                __half vu = rv[k];
                if (t <= 18)           LU[0] = __hfma(vu, w3s[t  ], LU[0]);
                if (t >= 1 && t <= 19) LU[1] = __hfma(vu, w3s[t-1], LU[1]);
                if (t >= 2 && t <= 20) LU[2] = __hfma(vu, w3s[t-2], LU[2]);
                if (t >= 3)            LU[3] = __hfma(vu, w3s[t-3], LU[3]);
            }
        }
    }
    __half2 G1P[4];
    #pragma unroll
    for (int j = 0; j < 4; j++) G1P[j] = __float2half2_rn(0.f);
    {   // vertical G1
        const uint4* h1T4 = (const uint4*)(smem_raw + OFF_H1T);
        int b = (c*CS_H1 + r0) >> 2;
        #pragma unroll
        for (int ch = 0; ch < 3; ch++) {
            uint4 q = h1T4[b + ch];
            __half2 rv[4] = { u2h2(q.x), u2h2(q.y), u2h2(q.z), u2h2(q.w) };
            #pragma unroll
            for (int k = 0; k < 4; k++) {
                int t = ch*4 + k;
                if (t > 9) break;
                __half2 v = rv[k];
                if (t <= 6)           G1P[0] = __hfma2(v, w1[t  ], G1P[0]);
                if (t >= 1 && t <= 7) G1P[1] = __hfma2(v, w1[t-1], G1P[1]);
                if (t >= 2 && t <= 8) G1P[2] = __hfma2(v, w1[t-2], G1P[2]);
                if (t >= 3)           G1P[3] = __hfma2(v, w1[t-3], G1P[3]);
            }
        }
    }

    float p_rc=0,p_nb=0,p_sxi=0,p_syp=0,p_ex=0,p_ey=0,p_ntex=0,p_stex=0;
    float p_nf=0,p_nfb=0,p_lf=0,p_mid=0,p_hf=0,p_syn=0,p_ic=0;

    int fb = r0*XFSTR + c;
    float x00=s_xf[fb],       x01=s_xf[fb+1],       x02=s_xf[fb+2];
    float y00=s_yf[fb],       y01=s_yf[fb+1],       y02=s_yf[fb+2];
    float x10=s_xf[fb+XFSTR], x11=s_xf[fb+XFSTR+1], x12=s_xf[fb+XFSTR+2];
    float y10=s_yf[fb+XFSTR], y11=s_yf[fb+XFSTR+1], y12=s_yf[fb+XFSTR+2];

    #pragma unroll
    for (int j = 0; j < 4; j++) {
        int fbn = fb + (j+2)*XFSTR;
        float x20=s_xf[fbn], x21=s_xf[fbn+1], x22=s_xf[fbn+2];
        float y20=s_yf[fbn], y21=s_yf[fbn+1], y22=s_yf[fbn+2];

        float gxi = (x02 - x00) + 2.f*(x12 - x10) + (x22 - x20);
        float gyi = (x20 - x00) + 2.f*(x21 - x01) + (x22 - x02);
        float lap_i = x01 + x10 + x12 + x21 - 4.f*x11;
        float gxp = (y02 - y00) + 2.f*(y12 - y10) + (y22 - y20);
        float gyp = (y20 - y00) + 2.f*(y21 - y01) + (y22 - y02);
        float lap_p = y01 + y10 + y12 + y21 - 4.f*y11;

        float xi = x11, yp = y11;

        int g = img + (oy + r0 + j)*IMW + (ox + c);
        float wv   = wt_g[g];
        float nprd = np_g[g];
        float nsyn = ns_g[g];

        p_rc += fabsf(yp*wv - xi*wv);

        bool body = (xi > 0.15f) & (xi < 0.85f);
        if (body) {
            p_nb += 1.f; p_sxi += xi; p_syp += yp;
            int b1 = min(max((int)(yp * (float)NBINS), 0), NBINS-1);
            atomicAdd(&s_hist[b1 >> 1], 1u << ((b1 & 1) * 16));
            int b2 = min(max((int)(xi * (float)NBINS), 0), NBINS-1);
            atomicAdd(&s_hist[NWORDS + (b2 >> 1)], 1u << ((b2 & 1) * 16));
        }

        p_ex += fabsf(gxp - gxi);
        p_ey += fabsf(gyp - gyi);

        float gmi = sqrtf(fmaf(gxi,gxi, gyi*gyi) + 1e-8f);
        float gmp = sqrtf(fmaf(gxp,gxp, gyp*gyp) + 1e-8f);

        bool tex = (gmi > 0.03f) & (gmi < 0.5f);
        if (tex) { p_ntex += 1.f; p_stex += fabsf(gmp - gmi); }

        bool flat = (gmi < 0.03f);
        if (flat) {
            p_nf += 1.f;
            p_hf += fabsf(fabsf(lap_p) - 0.3f*fabsf(lap_i));
            p_ic += fmaxf(gmp - 2.0f*gmi, 0.f);
            if (body) {
                p_nfb += 1.f;
                p_lf  += fabsf(__half2float(LU[j]));
                float low_i = __low2float(LIP[j]), low_p = __high2float(LIP[j]);
                float g1i   = __low2float(G1P[j]), g1p   = __high2float(G1P[j]);
                p_mid += fabsf(fabsf(g1p - low_p) - 0.3f*fabsf(g1i - low_i));
                p_syn += fabsf(nprd - nsyn);
            }
        }

        x00=x10; x01=x11; x02=x12; x10=x20; x11=x21; x12=x22;
        y00=y10; y01=y11; y02=y12; y10=y20; y11=y21; y12=y22;
    }

    // ---- block reduction of 15 partials ----
    float vals[NACC] = {p_rc, p_nb, p_sxi, p_syp, p_ex, p_ey, p_ntex, p_stex,
                        p_nf, p_nfb, p_lf, p_mid, p_hf, p_syn, p_ic};
    int lane = tid & 31, warp = tid >> 5;
    #pragma unroll
    for (int q = 0; q < NACC; q++) {
        float v = vals[q];
        #pragma unroll
        for (int o = 16; o > 0; o >>= 1) v += __shfl_down_sync(0xffffffffu, v, o);
        if (lane == 0) s_part[q][warp] = v;
    }
    __syncthreads();
    if (tid < NACC) {
        float s = 0.f;
        #pragma unroll
        for (int w = 0; w < 8; w++) s += s_part[tid][w];
        atomicAdd(&g_acc[tid], (double)s);
    }
    for (int i = tid; i < 2*NWORDS; i += NTHREADS) {
        unsigned int h = s_hist[i];
        if (h) atomicAdd(&g_histp[i], h);
    }

    // ---- last-block finalize ----
    __syncthreads();
    if (tid == 0) {
        __threadfence();
        unsigned t = atomicAdd(&g_ticket, 1u);
        s_last = (t == GRID_BLOCKS - 1);
    }
    __syncthreads();
    if (!s_last) return;
    __threadfence();

    unsigned int* s_cum = s_hist;
    const double nb = g_acc[1];

    for (int h = 0; h < 2; h++) {
        unsigned int w0 = g_histp[h*NWORDS + tid];
        unsigned int lo = w0 & 0xffffu, hi = w0 >> 16;
        unsigned int run = lo + hi;
        unsigned int v = run;
        #pragma unroll
        for (int o = 1; o < 32; o <<= 1) {
            unsigned int u = __shfl_up_sync(0xffffffffu, v, o);
            if (lane >= o) v += u;
        }
        __syncthreads();
        if (lane == 31) s_wtot[warp] = v;
        __syncthreads();
        unsigned int woff = 0;
        for (int w = 0; w < warp; w++) woff += s_wtot[w];
        unsigned int off = woff + v - run;
        s_cum[2*tid]   = off + lo;
        s_cum[2*tid+1] = off + run;
        __syncthreads();
        if (tid < 2) {
            double q = (tid == 0) ? 0.25 : 0.75;
            double pos = q * (nb - 1.0);
            int lo_i = 0, hi_i = NBINS - 1;
            while (lo_i < hi_i) {
                int m = (lo_i + hi_i) >> 1;
                if ((double)s_cum[m] > pos) hi_i = m; else lo_i = m + 1;
            }
            int b = lo_i;
            unsigned int cb = s_cum[b];
            unsigned int pv = b ? s_cum[b-1] : 0u;
            double cnt = (double)(cb - pv);
            double val = 0.0;
            if (cnt > 0.0) {
                double frac = (pos - (double)pv + 0.5) / cnt;
                frac = fmin(fmax(frac, 0.0), 1.0);
                val = ((double)b + frac) / (double)NBINS;
            }
            s_q[h*2 + tid] = val;
        }
        __syncthreads();
    }

    if (tid == 0) {
        const double n_all = (double)BATCH * IMH * IMW;
        double rc = g_acc[0] / n_all;
        double denb = fmax(nb, 1.0);
        double mean_in = g_acc[2] / denb;
        double mean_pr = g_acc[3] / denb;
        double dm  = mean_pr - mean_in;
        double d25 = s_q[0] - s_q[2];
        double d75 = s_q[1] - s_q[3];
        double hu  = dm*dm + 0.5*(d25*d25 + d75*d75);
        double loss_hu = (nb > 4096.0) ? hu : 0.0;
        double edge = g_acc[4]/n_all + g_acc[5]/n_all;
        double ntex = g_acc[6];
        double tex = (ntex > 100.0) ? g_acc[7]/fmax(ntex, 1.0) : 0.0;
        double nf = g_acc[8], nfb = g_acc[9];
        double lf  = (nfb > 100.0) ? g_acc[10]/fmax(nfb, 1.0) : 0.0;
        double mid = (nfb > 100.0) ? g_acc[11]/fmax(nfb, 1.0) : 0.0;
        double hf  = (nf  > 100.0) ? g_acc[12]/fmax(nf, 1.0)  : 0.0;
        double syn = (nfb > 100.0) ? g_acc[13]/fmax(nfb, 1.0) : 0.0;
        double ic  = (nf  > 100.0) ? g_acc[14]/fmax(nf, 1.0)  : 0.0;

        double total = 2.0*rc + 1.5*loss_hu + 1.0*edge + 0.8*tex
                     + 1.5*hf + 0.8*mid + 0.6*lf + 1.0*syn + 0.8*ic;
        out[0] = (float)total;
    }
    __syncthreads();

    for (int i = tid; i < 2*NWORDS; i += NTHREADS) g_histp[i] = 0u;
    if (tid < NACC) g_acc[tid] = 0.0;
    if (tid == 0) g_ticket = 0u;
}

extern "C" void kernel_launch(void* const* d_in, const int* in_sizes, int n_in,
                              void* d_out, int out_size) {
    const float* yp = (const float*)d_in[0];   // y_pred
    const float* np = (const float*)d_in[1];   // noise_pred
    const float* xi = (const float*)d_in[2];   // x_i
    // d_in[3] = x_ip1 (unused by reference)
    const float* xm = (const float*)d_in[4];   // x_mid
    const float* wt = (const float*)d_in[5];   // W
    const float* ns = (const float*)d_in[6];   // noise_synthetic
    float* out = (float*)d_out;

    cudaFuncSetAttribute(main_kernel,
                         cudaFuncAttributeMaxDynamicSharedMemorySize, SMEM_BYTES);

    dim3 grid(IMW / TILE, IMH / TILE, BATCH);
    main_kernel<<<grid, NTHREADS, SMEM_BYTES>>>(yp, np, xi, xm, wt, ns, out);
}